// round 5
// baseline (speedup 1.0000x reference)
#include <cuda_runtime.h>
#include <math.h>

// Problem constants
#define HIDN   1024
#define HEADS  8
#define HD     128
#define MDIM   8
#define NLAYERS 3
#define BATCH  8
#define SEQ    1024
#define ROWS   (BATCH * SEQ)          /* 8192 */
#define QKVW   (3 * HIDN)             /* 3072 */
#define INV_SQRT_D 0.08838834764831845f  /* 1/sqrt(128) */

// Scratch (device globals; no runtime allocation allowed)
__device__ float g_cur[ROWS * HIDN];        // 32 MB
__device__ float g_qkv[ROWS * QKVW];        // 96 MB
__device__ float g_o[ROWS * HIDN];          // 32 MB

// ---------------------------------------------------------------------------
// copy x -> cur (float4)
__global__ void copy_f4_kernel(const float4* __restrict__ src, float4* __restrict__ dst) {
    int i = blockIdx.x * blockDim.x + threadIdx.x;
    dst[i] = src[i];
}

// ---------------------------------------------------------------------------
// SGEMM: C[M,N] = A[M,K] @ B[K,N] + bias[N].  BM=BN=128, BK=16, 256 threads,
// 8x8 register microtile. M multiple of 128, N multiple of 128, K multiple of 16.
__global__ __launch_bounds__(256, 2)
void sgemm_bias_kernel(const float* __restrict__ A, const float* __restrict__ B,
                       const float* __restrict__ bias, float* __restrict__ C,
                       int N, int K) {
    __shared__ float As[16][132];   // A tile transposed: As[k][m], padded stride
    __shared__ float Bs[16][128];   // Bs[k][n]

    const int tid = threadIdx.x;
    const int tx = tid & 15;
    const int ty = tid >> 4;
    const int bm = blockIdx.y << 7;
    const int bn = blockIdx.x << 7;

    float acc[8][8];
#pragma unroll
    for (int i = 0; i < 8; i++)
#pragma unroll
        for (int j = 0; j < 8; j++) acc[i][j] = 0.f;

    for (int k0 = 0; k0 < K; k0 += 16) {
#pragma unroll
        for (int i = 0; i < 2; i++) {
            int id = tid + (i << 8);            // [0,512)
            int ar = id >> 2;                   // [0,128)
            int ac = (id & 3) << 2;             // {0,4,8,12}
            float4 av = *(const float4*)(A + (size_t)(bm + ar) * K + k0 + ac);
            As[ac + 0][ar] = av.x;
            As[ac + 1][ar] = av.y;
            As[ac + 2][ar] = av.z;
            As[ac + 3][ar] = av.w;
            int br = id >> 5;                   // [0,16)
            int bc = (id & 31) << 2;            // [0,128)
            *(float4*)&Bs[br][bc] = *(const float4*)(B + (size_t)(k0 + br) * N + bn + bc);
        }
        __syncthreads();
#pragma unroll
        for (int kk = 0; kk < 16; kk++) {
            float a[8], b[8];
            *(float4*)&a[0] = *(float4*)&As[kk][ty << 3];
            *(float4*)&a[4] = *(float4*)&As[kk][(ty << 3) + 4];
            *(float4*)&b[0] = *(float4*)&Bs[kk][tx << 3];
            *(float4*)&b[4] = *(float4*)&Bs[kk][(tx << 3) + 4];
#pragma unroll
            for (int i = 0; i < 8; i++)
#pragma unroll
                for (int j = 0; j < 8; j++)
                    acc[i][j] = fmaf(a[i], b[j], acc[i][j]);
        }
        __syncthreads();
    }

#pragma unroll
    for (int i = 0; i < 8; i++) {
        size_t row = (size_t)(bm + (ty << 3) + i);
#pragma unroll
        for (int j = 0; j < 8; j += 4) {
            int col = bn + (tx << 3) + j;
            float4 r;
            r.x = acc[i][j + 0] + bias[col + 0];
            r.y = acc[i][j + 1] + bias[col + 1];
            r.z = acc[i][j + 2] + bias[col + 2];
            r.w = acc[i][j + 3] + bias[col + 3];
            *(float4*)(C + row * N + col) = r;
        }
    }
}

// ---------------------------------------------------------------------------
// expmap0 applied in place to Q and K sections of qkv, per (row, head) vector
// of 128 floats. Q additionally scaled by 1/sqrt(HD). One warp per vector.
__global__ void expmap_qk_kernel(float* __restrict__ qkv) {
    int gw = (blockIdx.x * blockDim.x + threadIdx.x) >> 5;   // global warp id
    int lane = threadIdx.x & 31;
    int sec = gw & 1;            // 0 = Q, 1 = K
    int h = (gw >> 1) & 7;
    int row = gw >> 4;           // [0, 8192)
    float* base = qkv + (size_t)row * QKVW + sec * HIDN + h * HD + (lane << 2);
    float4 v = *(float4*)base;
    float ss = v.x * v.x + v.y * v.y + v.z * v.z + v.w * v.w;
#pragma unroll
    for (int m = 16; m; m >>= 1) ss += __shfl_xor_sync(0xffffffffu, ss, m);
    float n = fmaxf(sqrtf(ss), 1e-7f);
    float s = tanhf(n) / n;
    if (sec == 0) s *= INV_SQRT_D;
    v.x *= s; v.y *= s; v.z *= s; v.w *= s;
    *(float4*)base = v;
}

// ---------------------------------------------------------------------------
// Flash attention: per (b,h), Q tile of 128 rows, KV tiles of 64.
// 512 threads = 32(ty) x 16(tx). Each thread: 4 score rows (ty*4+i),
// score cols {tx+16j}, output cols tx*8..tx*8+7.
#define FA_BM 128
#define FA_BN 64
#define FA_SMEM ((128*128 + 64*132 + 64*128 + 128*65) * 4)   /* 165376 B */

__global__ __launch_bounds__(512, 1)
void flash_attn_kernel(const float* __restrict__ qkv, float* __restrict__ o) {
    extern __shared__ float sm[];
    float* Qs = sm;                         // 128 x 128
    float* Ks = Qs + 128 * 128;             // 64 x 132 (odd 16B-atom stride -> conflict-free)
    float* Vs = Ks + 64 * 132;              // 64 x 128
    float* Ps = Vs + 64 * 128;              // 128 x 65

    const int tid = threadIdx.x;
    const int tx = tid & 15;
    const int ty = tid >> 4;                // [0,32)
    const int bh = blockIdx.y;
    const int b = bh >> 3, h = bh & 7;
    const int q0 = blockIdx.x * FA_BM;
    const size_t rowbase = (size_t)b * SEQ;

    // Load Q tile
    for (int i = tid; i < FA_BM * 32; i += 512) {
        int r = i >> 5, c = (i & 31) << 2;
        *(float4*)&Qs[r * 128 + c] =
            *(const float4*)(qkv + (rowbase + q0 + r) * QKVW + h * HD + c);
    }

    float acc[4][8];
#pragma unroll
    for (int i = 0; i < 4; i++)
#pragma unroll
        for (int c = 0; c < 8; c++) acc[i][c] = 0.f;
    float mrow[4] = {-1e30f, -1e30f, -1e30f, -1e30f};
    float lrow[4] = {0.f, 0.f, 0.f, 0.f};

    for (int kt = 0; kt < SEQ; kt += FA_BN) {
        __syncthreads();   // previous tile's Ks/Vs/Ps reads done
        for (int i = tid; i < FA_BN * 32; i += 512) {
            int r = i >> 5, c = (i & 31) << 2;
            const float* src = qkv + (rowbase + kt + r) * QKVW + h * HD + c;
            *(float4*)&Ks[r * 132 + c] = *(const float4*)(src + HIDN);
            *(float4*)&Vs[r * 128 + c] = *(const float4*)(src + 2 * HIDN);
        }
        __syncthreads();

        // scores: s[i][j] = Qrow(ty*4+i) . Krow(tx+16j)
        float s[4][4];
#pragma unroll
        for (int i = 0; i < 4; i++)
#pragma unroll
            for (int j = 0; j < 4; j++) s[i][j] = 0.f;
#pragma unroll 8
        for (int d = 0; d < 128; d += 4) {
            float4 qv[4], kv[4];
#pragma unroll
            for (int i = 0; i < 4; i++) qv[i] = *(float4*)&Qs[(ty * 4 + i) * 128 + d];
#pragma unroll
            for (int j = 0; j < 4; j++) kv[j] = *(float4*)&Ks[(tx + 16 * j) * 132 + d];
#pragma unroll
            for (int i = 0; i < 4; i++)
#pragma unroll
                for (int j = 0; j < 4; j++) {
                    s[i][j] = fmaf(qv[i].x, kv[j].x, s[i][j]);
                    s[i][j] = fmaf(qv[i].y, kv[j].y, s[i][j]);
                    s[i][j] = fmaf(qv[i].z, kv[j].z, s[i][j]);
                    s[i][j] = fmaf(qv[i].w, kv[j].w, s[i][j]);
                }
        }

        // online softmax (row groups share ty; reduce across the 16 tx lanes)
#pragma unroll
        for (int i = 0; i < 4; i++) {
            float mx = fmaxf(fmaxf(s[i][0], s[i][1]), fmaxf(s[i][2], s[i][3]));
#pragma unroll
            for (int m = 8; m; m >>= 1) mx = fmaxf(mx, __shfl_xor_sync(0xffffffffu, mx, m));
            float mnew = fmaxf(mrow[i], mx);
            float scale = __expf(mrow[i] - mnew);
            mrow[i] = mnew;
            float ps = 0.f;
#pragma unroll
            for (int j = 0; j < 4; j++) { s[i][j] = __expf(s[i][j] - mnew); ps += s[i][j]; }
#pragma unroll
            for (int m = 8; m; m >>= 1) ps += __shfl_xor_sync(0xffffffffu, ps, m);
            lrow[i] = lrow[i] * scale + ps;
#pragma unroll
            for (int c = 0; c < 8; c++) acc[i][c] *= scale;
#pragma unroll
            for (int j = 0; j < 4; j++) Ps[(ty * 4 + i) * 65 + tx + 16 * j] = s[i][j];
        }
        __syncthreads();

        // acc += P @ V
#pragma unroll 4
        for (int j = 0; j < FA_BN; j++) {
            float4 v0 = *(float4*)&Vs[j * 128 + tx * 8];
            float4 v1 = *(float4*)&Vs[j * 128 + tx * 8 + 4];
#pragma unroll
            for (int i = 0; i < 4; i++) {
                float p = Ps[(ty * 4 + i) * 65 + j];
                acc[i][0] = fmaf(p, v0.x, acc[i][0]);
                acc[i][1] = fmaf(p, v0.y, acc[i][1]);
                acc[i][2] = fmaf(p, v0.z, acc[i][2]);
                acc[i][3] = fmaf(p, v0.w, acc[i][3]);
                acc[i][4] = fmaf(p, v1.x, acc[i][4]);
                acc[i][5] = fmaf(p, v1.y, acc[i][5]);
                acc[i][6] = fmaf(p, v1.z, acc[i][6]);
                acc[i][7] = fmaf(p, v1.w, acc[i][7]);
            }
        }
    }

    // epilogue: normalize, write o[b, q, h*HD + c]
#pragma unroll
    for (int i = 0; i < 4; i++) {
        float inv = 1.f / lrow[i];
        size_t row = rowbase + q0 + ty * 4 + i;
        float* dst = o + row * HIDN + h * HD + tx * 8;
        float4 r0, r1;
        r0.x = acc[i][0] * inv; r0.y = acc[i][1] * inv;
        r0.z = acc[i][2] * inv; r0.w = acc[i][3] * inv;
        r1.x = acc[i][4] * inv; r1.y = acc[i][5] * inv;
        r1.z = acc[i][6] * inv; r1.w = acc[i][7] * inv;
        *(float4*)dst = r0;
        *(float4*)(dst + 4) = r1;
    }
}

// ---------------------------------------------------------------------------
// Low-rank update: m = o_row @ W_pinv + b_pinv (8 dims);
// cur_row += m @ W_attn[l] + b_attn[l].  One block (256 thr) per row.
__global__ __launch_bounds__(256)
void lowrank_update_kernel(const float* __restrict__ o,
                           const float* __restrict__ Wp, const float* __restrict__ bp,
                           const float* __restrict__ Wa, const float* __restrict__ ba,
                           float* __restrict__ cur) {
    __shared__ float wred[8][8];
    __shared__ float msh[8];
    const int row = blockIdx.x;
    const float* orow = o + (size_t)row * HIDN;

    float part[8];
#pragma unroll
    for (int m = 0; m < 8; m++) part[m] = 0.f;
    for (int t = threadIdx.x; t < HIDN; t += 256) {
        float ov = orow[t];
        float4 w0 = *(const float4*)(Wp + t * 8);
        float4 w1 = *(const float4*)(Wp + t * 8 + 4);
        part[0] = fmaf(ov, w0.x, part[0]);
        part[1] = fmaf(ov, w0.y, part[1]);
        part[2] = fmaf(ov, w0.z, part[2]);
        part[3] = fmaf(ov, w0.w, part[3]);
        part[4] = fmaf(ov, w1.x, part[4]);
        part[5] = fmaf(ov, w1.y, part[5]);
        part[6] = fmaf(ov, w1.z, part[6]);
        part[7] = fmaf(ov, w1.w, part[7]);
    }
#pragma unroll
    for (int m = 0; m < 8; m++)
#pragma unroll
        for (int sh = 16; sh; sh >>= 1)
            part[m] += __shfl_xor_sync(0xffffffffu, part[m], sh);
    int warp = threadIdx.x >> 5, lane = threadIdx.x & 31;
    if (lane == 0) {
#pragma unroll
        for (int m = 0; m < 8; m++) wred[warp][m] = part[m];
    }
    __syncthreads();
    if (threadIdx.x < 8) {
        float s = bp[threadIdx.x];
#pragma unroll
        for (int w = 0; w < 8; w++) s += wred[w][threadIdx.x];
        msh[threadIdx.x] = s;
    }
    __syncthreads();

    int j = threadIdx.x * 4;   // each thread: one float4 of the 1024-wide row
    float4 u = *(const float4*)(ba + j);
#pragma unroll
    for (int m = 0; m < 8; m++) {
        float mv = msh[m];
        float4 w = *(const float4*)(Wa + m * HIDN + j);
        u.x = fmaf(mv, w.x, u.x);
        u.y = fmaf(mv, w.y, u.y);
        u.z = fmaf(mv, w.z, u.z);
        u.w = fmaf(mv, w.w, u.w);
    }
    float* cp = cur + (size_t)row * HIDN + j;
    float4 c = *(float4*)cp;
    c.x += u.x; c.y += u.y; c.z += u.z; c.w += u.w;
    *(float4*)cp = c;
}

// ---------------------------------------------------------------------------
extern "C" void kernel_launch(void* const* d_in, const int* in_sizes, int n_in,
                              void* d_out, int out_size) {
    (void)in_sizes; (void)n_in; (void)out_size;
    const float* x      = (const float*)d_in[0];
    const float* W_qkv  = (const float*)d_in[1];
    const float* b_qkv  = (const float*)d_in[2];
    const float* W_pinv = (const float*)d_in[3];
    const float* b_pinv = (const float*)d_in[4];
    const float* W_attn = (const float*)d_in[5];   // [3,8,1024]
    const float* b_attn = (const float*)d_in[6];   // [3,1024]
    const float* W_out  = (const float*)d_in[7];
    const float* b_out  = (const float*)d_in[8];
    float* out = (float*)d_out;

    float *cur, *qkv, *o;
    cudaGetSymbolAddress((void**)&cur, g_cur);
    cudaGetSymbolAddress((void**)&qkv, g_qkv);
    cudaGetSymbolAddress((void**)&o,   g_o);

    cudaFuncSetAttribute(flash_attn_kernel,
                         cudaFuncAttributeMaxDynamicSharedMemorySize, FA_SMEM);

    // cur = x
    copy_f4_kernel<<<ROWS * HIDN / 4 / 256, 256>>>((const float4*)x, (float4*)cur);

    for (int l = 0; l < NLAYERS; l++) {
        // qkv = cur @ W_qkv + b_qkv
        dim3 g1(QKVW / 128, ROWS / 128);
        sgemm_bias_kernel<<<g1, 256>>>(cur, W_qkv, b_qkv, qkv, QKVW, HIDN);

        // expmap0 on Q,K (Q also scaled by 1/sqrt(d))
        expmap_qk_kernel<<<ROWS * 16 / 8, 256>>>(qkv);   // 131072 warps

        // o = softmax(Qf Kf^T) V
        dim3 g2(SEQ / FA_BM, BATCH * HEADS);
        flash_attn_kernel<<<g2, 512, FA_SMEM>>>(qkv, o);

        // cur += (o @ W_pinv + b_pinv) @ W_attn[l] + b_attn[l]
        lowrank_update_kernel<<<ROWS, 256>>>(o, W_pinv, b_pinv,
                                             W_attn + (size_t)l * MDIM * HIDN,
                                             b_attn + (size_t)l * HIDN, cur);
    }

    // out = cur @ W_out + b_out
    dim3 g3(HIDN / 128, ROWS / 128);
    sgemm_bias_kernel<<<g3, 256>>>(cur, W_out, b_out, out, HIDN, HIDN);
}